// round 8
// baseline (speedup 1.0000x reference)
#include <cuda_runtime.h>

// Problem constants
#define BB   1024
#define TT   512
#define II   100
#define IIP  104    // padded input row stride (floats)
#define HH   150
#define HP   160    // padded hidden (mult of 32)
#define OO   3
#define WP   161    // weight smem pitch
#define XT   32     // xw rows per tile

// rnn kernel geometry (6-way k split)
#define NKC  6
#define KC   26     // k-chunk per sixth (6*26 = 156 >= 150)
#define K6   156
#define HROW 8      // hs row stride (rows 7 = pad)
#define RB   7      // batch rows per rnn CTA (147 CTAs)

// Output tuple layout: out, hidden, logits
#define HID_OFF  ((size_t)BB * TT * OO)
#define LOG_OFF  (HID_OFF + (size_t)BB * TT * HH)

// Scratch: input projection xw[bt][HP] (~335 MB)
__device__ float g_xw[(size_t)BB * TT * HP];

__device__ __forceinline__ unsigned smem_u32(const void* p) {
    return (unsigned)__cvta_generic_to_shared(p);
}

// ---------------------------------------------------------------------------
// Kernel 1: xw[bt][j] = sum_i x[bt][i] * W_ih[j][i].
// 640 threads = (j in [0,160), rgrp in [0,4)): 1 j x 8 rows per thread ->
// only 8 accumulators, ~45 regs, 2 CTAs/SM = 40 warps/SM (latency hiding).
// cp.async double-buffered x staging.
// ---------------------------------------------------------------------------
__global__ void __launch_bounds__(640, 2) xw_kernel(const float* __restrict__ x,
                                                    const float* __restrict__ W_ih) {
    extern __shared__ float sm[];
    float* WihT = sm;                 // [II][WP]
    float* xs0  = sm + II * WP;       // [XT][IIP]
    float* xs1  = xs0 + XT * IIP;     // [XT][IIP]
    const int tid = threadIdx.x;

    for (int i = tid; i < II * WP; i += 640) WihT[i] = 0.f;
    __syncthreads();
    for (int idx = tid; idx < HH * II; idx += 640) {
        const int h = idx / II, i = idx - h * II;
        WihT[i * WP + h] = W_ih[idx];
    }

    const int j    = tid % HP;        // output column
    const int rgrp = tid / HP;        // rows rgrp*8 .. rgrp*8+7
    const int nTiles = (BB * TT) / XT;

    // async-stage: 32 rows x 25 16B chunks
    auto stage = [&](float* dst, int tile) {
        const int bt0 = tile * XT;
#pragma unroll
        for (int s = 0; s < 2; s++) {
            const int c = tid + s * 640;
            if (c < XT * 25) {
                const int r = c / 25, k = c - r * 25;
                const float* src = x + (size_t)(bt0 + r) * II + k * 4;
                const unsigned d = smem_u32(dst + r * IIP + k * 4);
                asm volatile("cp.async.ca.shared.global [%0], [%1], 16;"
                             :: "r"(d), "l"(src));
            }
        }
    };

    stage(xs0, blockIdx.x);
    asm volatile("cp.async.commit_group;");
    asm volatile("cp.async.wait_group 0;");
    __syncthreads();

    int buf = 0;
    for (int tile = blockIdx.x; tile < nTiles; tile += gridDim.x) {
        const int next = tile + gridDim.x;
        float* cur = buf ? xs1 : xs0;
        float* oth = buf ? xs0 : xs1;
        if (next < nTiles) stage(oth, next);
        asm volatile("cp.async.commit_group;");

        const int bt0 = tile * XT;
        float acc[8];
#pragma unroll
        for (int r = 0; r < 8; r++) acc[r] = 0.f;

        const float* xrow = cur + rgrp * 8 * IIP;
#pragma unroll
        for (int kq = 0; kq < II / 4; kq++) {
            const float w0 = WihT[(4 * kq + 0) * WP + j];
            const float w1 = WihT[(4 * kq + 1) * WP + j];
            const float w2 = WihT[(4 * kq + 2) * WP + j];
            const float w3 = WihT[(4 * kq + 3) * WP + j];
#pragma unroll
            for (int r = 0; r < 8; r++) {
                const float4 xv = *(const float4*)&xrow[r * IIP + 4 * kq];  // broadcast
                acc[r] = fmaf(xv.x, w0, acc[r]);
                acc[r] = fmaf(xv.y, w1, acc[r]);
                acc[r] = fmaf(xv.z, w2, acc[r]);
                acc[r] = fmaf(xv.w, w3, acc[r]);
            }
        }
#pragma unroll
        for (int r = 0; r < 8; r++)
            g_xw[(size_t)(bt0 + rgrp * 8 + r) * HP + j] = acc[r];

        asm volatile("cp.async.wait_group 0;");
        __syncthreads();
        buf ^= 1;
    }
}

// ---------------------------------------------------------------------------
// Kernel 2: sequential RNN. 147 CTAs x 7 rows, 960 threads (30 warps — more
// warps to hide the per-step stall window). Thread = (j = tid%160,
// kc = tid/160 in [0,6)): W_hh[j][26kc..+25] in registers (~50 regs).
// h transposed hs[k][row], warp-uniform broadcast LDS (load-bearing).
// Cross-kc reduction via smem psum, 2 barriers/step.
// ---------------------------------------------------------------------------
__global__ void __launch_bounds__(960, 1) rnn_kernel(const float* __restrict__ h0,
                                                     const float* __restrict__ W_hh,
                                                     float* __restrict__ out) {
    __shared__ __align__(16) float hs[2][K6 * HROW];   // [buf][k][row]
    __shared__ float psum[NKC][RB * HP];                // [kc][r*HP+j]

    const int tid = threadIdx.x;
    const int j   = tid % HP;
    const int kc  = tid / HP;        // [0,6)
    const int b0  = blockIdx.x * RB;
    const int nrows = (BB - b0 < RB) ? (BB - b0) : RB;

    // --- one-time: weights into registers ---
    float w[KC];
#pragma unroll
    for (int i = 0; i < KC; i++) {
        const int k = KC * kc + i;
        w[i] = (j < HH && k < HH) ? W_hh[j * HH + k] : 0.f;
    }

    // --- init hs: zero both buffers, fill valid rows of h0 (transposed) ---
    for (int idx = tid; idx < 2 * K6 * HROW; idx += 960) ((float*)hs)[idx] = 0.f;
    __syncthreads();
    for (int idx = tid; idx < HH * nrows; idx += 960) {
        const int k = idx / nrows, r = idx - k * nrows;
        hs[0][k * HROW + r] = h0[(b0 + r) * HH + k];
    }
    __syncthreads();

    // reduction rows: kc 0..5 own rows 0..5; kc==0 additionally owns row 6.
    const int r_lo = kc;
    const bool own_hi = (kc == 0);
    const int r_hi = 6;
    const bool v_lo = (r_lo < nrows);
    const bool v_hi = own_hi && (r_hi < nrows);
    const int row_lo = v_lo ? r_lo : 0;
    const int row_hi = v_hi ? r_hi : 0;
    const float* px0 = g_xw + ((size_t)(b0 + row_lo) * TT) * HP + j;
    const float* px1 = g_xw + ((size_t)(b0 + row_hi) * TT) * HP + j;
    float xw0 = px0[0];
    float xw1 = px1[0];

    float* hid_out = out + HID_OFF;
    int cur = 0;

    for (int t = 0; t < TT; t++) {
        // prefetch next step's xw (latency hidden by FMA loop)
        float nx0 = 0.f, nx1 = 0.f;
        if (t + 1 < TT) { nx0 = px0[HP]; nx1 = px1[HP]; }

        // --- main FMA loop: 7 rows x 26 k, weights in regs, h broadcast ---
        const float* hc = &hs[cur][(KC * kc) * HROW];
        float a0 = 0.f, a1 = 0.f, a2 = 0.f, a3 = 0.f;
        float a4 = 0.f, a5 = 0.f, a6 = 0.f;
#pragma unroll
        for (int i = 0; i < KC; i++) {
            const float4 va = *(const float4*)(hc + i * HROW);       // rows 0-3 (broadcast)
            const float4 vb = *(const float4*)(hc + i * HROW + 4);   // rows 4-7
            a0 = fmaf(w[i], va.x, a0);
            a1 = fmaf(w[i], va.y, a1);
            a2 = fmaf(w[i], va.z, a2);
            a3 = fmaf(w[i], va.w, a3);
            a4 = fmaf(w[i], vb.x, a4);
            a5 = fmaf(w[i], vb.y, a5);
            a6 = fmaf(w[i], vb.z, a6);
        }

        // --- write partials ---
        float* ps = psum[kc] + j;
        ps[0 * HP] = a0; ps[1 * HP] = a1; ps[2 * HP] = a2; ps[3 * HP] = a3;
        ps[4 * HP] = a4; ps[5 * HP] = a5; ps[6 * HP] = a6;
        __syncthreads();

        // --- reduce owned rows across 6 kc partials + xw, relu ---
        float s0 = psum[0][r_lo * HP + j] + psum[1][r_lo * HP + j]
                 + psum[2][r_lo * HP + j] + psum[3][r_lo * HP + j]
                 + psum[4][r_lo * HP + j] + psum[5][r_lo * HP + j] + xw0;
        s0 = fmaxf(s0, 0.f);
        float s1 = 0.f;
        if (own_hi) {
            s1 = psum[0][r_hi * HP + j] + psum[1][r_hi * HP + j]
               + psum[2][r_hi * HP + j] + psum[3][r_hi * HP + j]
               + psum[4][r_hi * HP + j] + psum[5][r_hi * HP + j] + xw1;
            s1 = fmaxf(s1, 0.f);
        }

        // --- write next h state (transposed) + hidden output ---
        float* hn = hs[cur ^ 1];
        if (j < HH) {
            hn[j * HROW + r_lo] = s0;
            if (v_lo) hid_out[((size_t)(b0 + r_lo) * TT + t) * HH + j] = s0;
            if (own_hi) {
                hn[j * HROW + r_hi] = s1;
                if (v_hi) hid_out[((size_t)(b0 + r_hi) * TT + t) * HH + j] = s1;
            }
        }

        xw0 = nx0; xw1 = nx1;
        px0 += HP; px1 += HP;
        __syncthreads();
        cur ^= 1;
    }
}

// ---------------------------------------------------------------------------
// Kernel 3: logits = hidden @ W_fc^T; out = one_hot(argmax(logits+g)).
// ---------------------------------------------------------------------------
__global__ void __launch_bounds__(256) post_kernel(const float* __restrict__ g,
                                                   const float* __restrict__ W_fc,
                                                   float* __restrict__ out) {
    __shared__ float wfc[OO * HP];
    const int tid = threadIdx.x;
    for (int i = tid; i < OO * HP; i += 256) {
        const int o = i / HP, k = i - o * HP;
        wfc[i] = (k < HH) ? W_fc[o * HH + k] : 0.f;
    }
    __syncthreads();

    const int warp = tid >> 5, lane = tid & 31;
    const size_t bt = (size_t)blockIdx.x * 8 + warp;
    const float* hid = out + HID_OFF + bt * HH;

    float hv[5];
#pragma unroll
    for (int m = 0; m < 5; m++) {
        const int k = lane + 32 * m;
        hv[m] = (k < HH) ? hid[k] : 0.f;
    }
    float p[OO];
#pragma unroll
    for (int o = 0; o < OO; o++) {
        float s = 0.f;
#pragma unroll
        for (int m = 0; m < 5; m++)
            s = fmaf(hv[m], wfc[o * HP + lane + 32 * m], s);
#pragma unroll
        for (int off = 16; off > 0; off >>= 1)
            s += __shfl_xor_sync(0xffffffffu, s, off);
        p[o] = s;
    }
    if (lane == 0) {
        const float z0 = p[0] + g[bt * OO + 0];
        const float z1 = p[1] + g[bt * OO + 1];
        const float z2 = p[2] + g[bt * OO + 2];
        int idx = 0; float best = z0;
        if (z1 > best) { best = z1; idx = 1; }
        if (z2 > best) { best = z2; idx = 2; }
        float* op = out + bt * OO;
        op[0] = (idx == 0) ? 1.f : 0.f;
        op[1] = (idx == 1) ? 1.f : 0.f;
        op[2] = (idx == 2) ? 1.f : 0.f;
        float* lp = out + LOG_OFF + bt * OO;
        lp[0] = p[0]; lp[1] = p[1]; lp[2] = p[2];
    }
}

// ---------------------------------------------------------------------------
extern "C" void kernel_launch(void* const* d_in, const int* in_sizes, int n_in,
                              void* d_out, int out_size) {
    const float* x    = (const float*)d_in[0];
    const float* h0   = (const float*)d_in[1];
    const float* g    = (const float*)d_in[2];
    const float* W_ih = (const float*)d_in[3];
    const float* W_hh = (const float*)d_in[4];
    const float* W_fc = (const float*)d_in[5];
    float* out = (float*)d_out;

    const int xw_smem = (II * WP + 2 * XT * IIP) * (int)sizeof(float);   // ~91 KB
    cudaFuncSetAttribute(xw_kernel, cudaFuncAttributeMaxDynamicSharedMemorySize, xw_smem);

    xw_kernel<<<296, 640, xw_smem>>>(x, W_ih);               // 2 CTAs/SM, persistent
    rnn_kernel<<<(BB + RB - 1) / RB, 960>>>(h0, W_hh, out);  // 147 CTAs, 30 warps
    post_kernel<<<(BB * TT) / 8, 256>>>(g, W_fc, out);
}

// round 9
// speedup vs baseline: 1.2445x; 1.2445x over previous
#include <cuda_runtime.h>

// Problem constants
#define BB   1024
#define TT   512
#define II   100
#define IIP  104    // padded input row stride (floats)
#define HH   150
#define HP   160    // padded hidden (mult of 32)
#define OO   3
#define WP   161    // weight smem pitch
#define XT   32     // xw rows per tile

// rnn kernel geometry: 6-way k split x 2 j's per thread
#define NKC  6
#define KC   25     // 6*25 = 150 exactly
#define HROW 8      // hs row stride (row 7 = pad)
#define RB   7      // batch rows per rnn CTA (147 CTAs)

// Output tuple layout: out, hidden, logits
#define HID_OFF  ((size_t)BB * TT * OO)
#define LOG_OFF  (HID_OFF + (size_t)BB * TT * HH)

// Scratch: input projection xw[bt][HP] (~335 MB)
__device__ float g_xw[(size_t)BB * TT * HP];

__device__ __forceinline__ unsigned smem_u32(const void* p) {
    return (unsigned)__cvta_generic_to_shared(p);
}

// ---------------------------------------------------------------------------
// Kernel 1: xw[bt][j] = sum_i x[bt][i] * W_ih[j][i].
// R7 design verbatim (measured 493us): 320 threads, 2 j's x 8 rows per
// thread, cp.async double-buffered x staging.
// ---------------------------------------------------------------------------
__global__ void __launch_bounds__(320, 2) xw_kernel(const float* __restrict__ x,
                                                    const float* __restrict__ W_ih) {
    extern __shared__ float sm[];
    float* WihT = sm;                 // [II][WP]
    float* xs0  = sm + II * WP;       // [XT][IIP]
    float* xs1  = xs0 + XT * IIP;     // [XT][IIP]
    const int tid = threadIdx.x;

    for (int i = tid; i < II * WP; i += 320) WihT[i] = 0.f;
    __syncthreads();
    for (int idx = tid; idx < HH * II; idx += 320) {
        const int h = idx / II, i = idx - h * II;
        WihT[i * WP + h] = W_ih[idx];
    }

    const int jp   = tid % 80;        // j pair: {jp, jp+80}
    const int half = tid / 80;        // rows half*8 .. half*8+7
    const int nTiles = (BB * TT) / XT;

    auto stage = [&](float* dst, int tile) {
        const int bt0 = tile * XT;
#pragma unroll
        for (int s = 0; s < 3; s++) {
            const int c = tid + s * 320;
            if (c < XT * 25) {
                const int r = c / 25, k = c - r * 25;
                const float* src = x + (size_t)(bt0 + r) * II + k * 4;
                const unsigned d = smem_u32(dst + r * IIP + k * 4);
                asm volatile("cp.async.ca.shared.global [%0], [%1], 16;"
                             :: "r"(d), "l"(src));
            }
        }
    };

    stage(xs0, blockIdx.x);
    asm volatile("cp.async.commit_group;");
    asm volatile("cp.async.wait_group 0;");
    __syncthreads();

    int buf = 0;
    for (int tile = blockIdx.x; tile < nTiles; tile += gridDim.x) {
        const int next = tile + gridDim.x;
        float* cur = buf ? xs1 : xs0;
        float* oth = buf ? xs0 : xs1;
        if (next < nTiles) stage(oth, next);
        asm volatile("cp.async.commit_group;");

        const int bt0 = tile * XT;
        float acc0[8], acc1[8];
#pragma unroll
        for (int r = 0; r < 8; r++) { acc0[r] = 0.f; acc1[r] = 0.f; }

        const float* xrow = cur + half * 8 * IIP;
#pragma unroll
        for (int kq = 0; kq < II / 4; kq++) {
            const float wa0 = WihT[(4 * kq + 0) * WP + jp];
            const float wa1 = WihT[(4 * kq + 1) * WP + jp];
            const float wa2 = WihT[(4 * kq + 2) * WP + jp];
            const float wa3 = WihT[(4 * kq + 3) * WP + jp];
            const float wb0 = WihT[(4 * kq + 0) * WP + jp + 80];
            const float wb1 = WihT[(4 * kq + 1) * WP + jp + 80];
            const float wb2 = WihT[(4 * kq + 2) * WP + jp + 80];
            const float wb3 = WihT[(4 * kq + 3) * WP + jp + 80];
#pragma unroll
            for (int r = 0; r < 8; r++) {
                const float4 xv = *(const float4*)&xrow[r * IIP + 4 * kq];  // broadcast
                acc0[r] = fmaf(xv.x, wa0, acc0[r]);
                acc0[r] = fmaf(xv.y, wa1, acc0[r]);
                acc0[r] = fmaf(xv.z, wa2, acc0[r]);
                acc0[r] = fmaf(xv.w, wa3, acc0[r]);
                acc1[r] = fmaf(xv.x, wb0, acc1[r]);
                acc1[r] = fmaf(xv.y, wb1, acc1[r]);
                acc1[r] = fmaf(xv.z, wb2, acc1[r]);
                acc1[r] = fmaf(xv.w, wb3, acc1[r]);
            }
        }
#pragma unroll
        for (int r = 0; r < 8; r++) {
            const size_t row = (size_t)(bt0 + half * 8 + r);
            g_xw[row * HP + jp]      = acc0[r];
            g_xw[row * HP + jp + 80] = acc1[r];
        }

        asm volatile("cp.async.wait_group 0;");
        __syncthreads();
        buf ^= 1;
    }
}

// ---------------------------------------------------------------------------
// Kernel 2: sequential RNN. 147 CTAs x 7 rows, 480 threads (15 warps).
// Thread = (jp = tid%80, kc = tid/80 in [0,6)): handles TWO j's (jp, jp+80)
// so each broadcast h-load feeds 14 FMA (halves LDS wavefronts per FMA vs
// R5/R7). W_hh[{jp,jp+80}][25kc..+24] in registers. Cross-kc reduction via
// smem psum, 2 barriers/step.
// ---------------------------------------------------------------------------
__global__ void __launch_bounds__(480, 1) rnn_kernel(const float* __restrict__ h0,
                                                     const float* __restrict__ W_hh,
                                                     float* __restrict__ out) {
    __shared__ __align__(16) float hs[2][HH * HROW];   // [buf][k][row]
    __shared__ float psum[NKC][RB * HP];                // [kc][r*HP+j]

    const int tid = threadIdx.x;
    const int jp  = tid % 80;        // j pair: {jp, jp+80}
    const int kc  = tid / 80;        // [0,6)
    const int j1  = jp + 80;
    const bool j1v = (j1 < HH);      // jp < 70
    const int b0  = blockIdx.x * RB;
    const int nrows = (BB - b0 < RB) ? (BB - b0) : RB;

    // --- one-time: weights into registers (k range exact: 6*25 = 150) ---
    float w0[KC], w1[KC];
#pragma unroll
    for (int i = 0; i < KC; i++) {
        const int k = KC * kc + i;
        w0[i] = W_hh[jp * HH + k];
        w1[i] = j1v ? W_hh[j1 * HH + k] : 0.f;
    }

    // --- init hs: zero both buffers, fill valid rows of h0 (transposed) ---
    for (int idx = tid; idx < 2 * HH * HROW; idx += 480) ((float*)hs)[idx] = 0.f;
    __syncthreads();
    for (int idx = tid; idx < HH * nrows; idx += 480) {
        const int k = idx / nrows, r = idx - k * nrows;
        hs[0][k * HROW + r] = h0[(b0 + r) * HH + k];
    }
    __syncthreads();

    // reduction rows: kc owns row kc; kc==0 additionally owns row 6.
    const int r_lo = kc;
    const bool own_hi = (kc == 0);
    const int r_hi = 6;
    const bool v_lo = (r_lo < nrows);
    const bool v_hi = own_hi && (r_hi < nrows);
    const int row_lo = v_lo ? r_lo : 0;   // clamp for safe addressing
    const int row_hi = v_hi ? r_hi : 0;
    const float* px0 = g_xw + ((size_t)(b0 + row_lo) * TT) * HP + jp;
    const float* px1 = g_xw + ((size_t)(b0 + row_hi) * TT) * HP + jp;
    float xw00 = px0[0],  xw01 = px0[80];
    float xw10 = px1[0],  xw11 = px1[80];

    float* hid_out = out + HID_OFF;
    int cur = 0;

    for (int t = 0; t < TT; t++) {
        // prefetch next step's xw (latency hidden by FMA loop)
        float n00 = 0.f, n01 = 0.f, n10 = 0.f, n11 = 0.f;
        if (t + 1 < TT) {
            n00 = px0[HP]; n01 = px0[HP + 80];
            n10 = px1[HP]; n11 = px1[HP + 80];
        }

        // --- main FMA loop: 2 j's x 7 rows x 25 k; h broadcast from smem ---
        const float* hc = &hs[cur][(KC * kc) * HROW];
        float a0 = 0.f, a1 = 0.f, a2 = 0.f, a3 = 0.f, a4 = 0.f, a5 = 0.f, a6 = 0.f;
        float c0 = 0.f, c1 = 0.f, c2 = 0.f, c3 = 0.f, c4 = 0.f, c5 = 0.f, c6 = 0.f;
#pragma unroll
        for (int i = 0; i < KC; i++) {
            const float4 va = *(const float4*)(hc + i * HROW);       // rows 0-3 (broadcast)
            const float4 vb = *(const float4*)(hc + i * HROW + 4);   // rows 4-6
            a0 = fmaf(w0[i], va.x, a0);  c0 = fmaf(w1[i], va.x, c0);
            a1 = fmaf(w0[i], va.y, a1);  c1 = fmaf(w1[i], va.y, c1);
            a2 = fmaf(w0[i], va.z, a2);  c2 = fmaf(w1[i], va.z, c2);
            a3 = fmaf(w0[i], va.w, a3);  c3 = fmaf(w1[i], va.w, c3);
            a4 = fmaf(w0[i], vb.x, a4);  c4 = fmaf(w1[i], vb.x, c4);
            a5 = fmaf(w0[i], vb.y, a5);  c5 = fmaf(w1[i], vb.y, c5);
            a6 = fmaf(w0[i], vb.z, a6);  c6 = fmaf(w1[i], vb.z, c6);
        }

        // --- write partials (both j's) ---
        float* ps = psum[kc] + jp;
        ps[0 * HP] = a0; ps[1 * HP] = a1; ps[2 * HP] = a2; ps[3 * HP] = a3;
        ps[4 * HP] = a4; ps[5 * HP] = a5; ps[6 * HP] = a6;
        float* ps1 = ps + 80;
        ps1[0 * HP] = c0; ps1[1 * HP] = c1; ps1[2 * HP] = c2; ps1[3 * HP] = c3;
        ps1[4 * HP] = c4; ps1[5 * HP] = c5; ps1[6 * HP] = c6;
        __syncthreads();

        // --- reduce owned rows across 6 kc partials + xw, relu ---
        float s00 = psum[0][r_lo * HP + jp] + psum[1][r_lo * HP + jp]
                  + psum[2][r_lo * HP + jp] + psum[3][r_lo * HP + jp]
                  + psum[4][r_lo * HP + jp] + psum[5][r_lo * HP + jp] + xw00;
        float s01 = psum[0][r_lo * HP + j1] + psum[1][r_lo * HP + j1]
                  + psum[2][r_lo * HP + j1] + psum[3][r_lo * HP + j1]
                  + psum[4][r_lo * HP + j1] + psum[5][r_lo * HP + j1] + xw01;
        s00 = fmaxf(s00, 0.f);
        s01 = fmaxf(s01, 0.f);
        float s10 = 0.f, s11 = 0.f;
        if (own_hi) {
            s10 = psum[0][r_hi * HP + jp] + psum[1][r_hi * HP + jp]
                + psum[2][r_hi * HP + jp] + psum[3][r_hi * HP + jp]
                + psum[4][r_hi * HP + jp] + psum[5][r_hi * HP + jp] + xw10;
            s11 = psum[0][r_hi * HP + j1] + psum[1][r_hi * HP + j1]
                + psum[2][r_hi * HP + j1] + psum[3][r_hi * HP + j1]
                + psum[4][r_hi * HP + j1] + psum[5][r_hi * HP + j1] + xw11;
            s10 = fmaxf(s10, 0.f);
            s11 = fmaxf(s11, 0.f);
        }

        // --- write next h state (transposed) + hidden output ---
        float* hn = hs[cur ^ 1];
        hn[jp * HROW + r_lo] = s00;
        if (j1v) hn[j1 * HROW + r_lo] = s01;
        if (v_lo) {
            hid_out[((size_t)(b0 + r_lo) * TT + t) * HH + jp] = s00;
            if (j1v) hid_out[((size_t)(b0 + r_lo) * TT + t) * HH + j1] = s01;
        }
        if (own_hi) {
            hn[jp * HROW + r_hi] = s10;
            if (j1v) hn[j1 * HROW + r_hi] = s11;
            if (v_hi) {
                hid_out[((size_t)(b0 + r_hi) * TT + t) * HH + jp] = s10;
                if (j1v) hid_out[((size_t)(b0 + r_hi) * TT + t) * HH + j1] = s11;
            }
        }

        xw00 = n00; xw01 = n01; xw10 = n10; xw11 = n11;
        px0 += HP; px1 += HP;
        __syncthreads();
        cur ^= 1;
    }
}

// ---------------------------------------------------------------------------
// Kernel 3: logits = hidden @ W_fc^T; out = one_hot(argmax(logits+g)).
// ---------------------------------------------------------------------------
__global__ void __launch_bounds__(256) post_kernel(const float* __restrict__ g,
                                                   const float* __restrict__ W_fc,
                                                   float* __restrict__ out) {
    __shared__ float wfc[OO * HP];
    const int tid = threadIdx.x;
    for (int i = tid; i < OO * HP; i += 256) {
        const int o = i / HP, k = i - o * HP;
        wfc[i] = (k < HH) ? W_fc[o * HH + k] : 0.f;
    }
    __syncthreads();

    const int warp = tid >> 5, lane = tid & 31;
    const size_t bt = (size_t)blockIdx.x * 8 + warp;
    const float* hid = out + HID_OFF + bt * HH;

    float hv[5];
#pragma unroll
    for (int m = 0; m < 5; m++) {
        const int k = lane + 32 * m;
        hv[m] = (k < HH) ? hid[k] : 0.f;
    }
    float p[OO];
#pragma unroll
    for (int o = 0; o < OO; o++) {
        float s = 0.f;
#pragma unroll
        for (int m = 0; m < 5; m++)
            s = fmaf(hv[m], wfc[o * HP + lane + 32 * m], s);
#pragma unroll
        for (int off = 16; off > 0; off >>= 1)
            s += __shfl_xor_sync(0xffffffffu, s, off);
        p[o] = s;
    }
    if (lane == 0) {
        const float z0 = p[0] + g[bt * OO + 0];
        const float z1 = p[1] + g[bt * OO + 1];
        const float z2 = p[2] + g[bt * OO + 2];
        int idx = 0; float best = z0;
        if (z1 > best) { best = z1; idx = 1; }
        if (z2 > best) { best = z2; idx = 2; }
        float* op = out + bt * OO;
        op[0] = (idx == 0) ? 1.f : 0.f;
        op[1] = (idx == 1) ? 1.f : 0.f;
        op[2] = (idx == 2) ? 1.f : 0.f;
        float* lp = out + LOG_OFF + bt * OO;
        lp[0] = p[0]; lp[1] = p[1]; lp[2] = p[2];
    }
}

// ---------------------------------------------------------------------------
extern "C" void kernel_launch(void* const* d_in, const int* in_sizes, int n_in,
                              void* d_out, int out_size) {
    const float* x    = (const float*)d_in[0];
    const float* h0   = (const float*)d_in[1];
    const float* g    = (const float*)d_in[2];
    const float* W_ih = (const float*)d_in[3];
    const float* W_hh = (const float*)d_in[4];
    const float* W_fc = (const float*)d_in[5];
    float* out = (float*)d_out;

    const int xw_smem = (II * WP + 2 * XT * IIP) * (int)sizeof(float);   // ~91 KB
    cudaFuncSetAttribute(xw_kernel, cudaFuncAttributeMaxDynamicSharedMemorySize, xw_smem);

    xw_kernel<<<2048, 320, xw_smem>>>(x, W_ih);
    rnn_kernel<<<(BB + RB - 1) / RB, 480>>>(h0, W_hh, out);   // 147 CTAs
    post_kernel<<<(BB * TT) / 8, 256>>>(g, W_fc, out);
}